// round 5
// baseline (speedup 1.0000x reference)
#include <cuda_runtime.h>

#define BATCH 4
#define CH    64
#define H     256
#define WID   256
#define HW    (H*WID)
#define CHW   (CH*HW)
#define TILE_X 32

// scratch (allocation-free: __device__ globals)
__device__ float g_s[BATCH*HW];        // per-pixel vertical shift s
__device__ float g_x2[BATCH*CHW];      // warped image

// ---------------------------------------------------------------------------
// Kernel A: per-pixel channel max -> depth -> s, and vertical bilinear warp x2
// ---------------------------------------------------------------------------
__global__ __launch_bounds__(256) void prep_kernel(const float* __restrict__ X) {
    int idx = blockIdx.x * 256 + threadIdx.x;
    if (idx >= BATCH*HW) return;
    int b   = idx / HW;
    int rem = idx - b*HW;
    int y   = rem / WID;
    int x   = rem - y*WID;

    const float* Xpix = X + b*CHW + y*WID + x;
    float m = -1e30f;
    #pragma unroll 8
    for (int c = 0; c < CH; c++) m = fmaxf(m, Xpix[c*HW]);

    float depth = fminf(fmaxf(m, 1.0f), 50.0f);
    float s = 50.0f / (2.0f * depth);          // FOCAL/(downsample*depth)
    g_s[idx] = s;

    float ys = (float)y - s;
    float fy = floorf(ys);
    int   y0 = (int)fy;
    float w1 = ys - fy;
    float w0 = 1.0f - w1;

    bool ok0 = (y0   >= 0) && (y0   < H);
    bool ok1 = (y0+1 >= 0) && (y0+1 < H);
    const float* Xc0 = X + b*CHW + (ok0 ? y0   : 0)*WID + x;
    const float* Xc1 = X + b*CHW + (ok1 ? y0+1 : 0)*WID + x;
    float* X2p = g_x2 + b*CHW + y*WID + x;

    #pragma unroll 4
    for (int c = 0; c < CH; c++) {
        float a  = ok0 ? Xc0[c*HW] : 0.0f;
        float bb = ok1 ? Xc1[c*HW] : 0.0f;
        X2p[c*HW] = w0*a + w1*bb;
    }
}

// ---------------------------------------------------------------------------
// Kernel B: fused dual 3x3 conv (upper on X, lower on gathered/interp'd x2),
//           out = min(upper, lower).
// Block: 1 batch, 1 row, 32-px tile, all 64 out channels. 128 threads:
//   thread = (ogroup of 8 outch) x (pair of 2 pixels).
// Per input channel c: stage W[:,c,:,:] (576), upper halo rows (3x34), and
// per-pixel lower taps v (32x9) in shared; then 9-tap x 8-outch FMA loop.
// ---------------------------------------------------------------------------
__global__ __launch_bounds__(128) void conv_min_kernel(const float* __restrict__ X,
                                                       const float* __restrict__ Wg,
                                                       float* __restrict__ Out) {
    __shared__ float sW[CH*9];            // weights for current c
    __shared__ float sU[3][TILE_X+2];     // upper halo rows
    __shared__ float sV[TILE_X][9];       // lower interpolated taps

    const int x0 = blockIdx.x * TILE_X;
    const int y  = blockIdx.y;
    const int b  = blockIdx.z;
    const int t  = threadIdx.x;

    // gather parameters for t < 32 (one thread per tile pixel)
    int   iy0 = 0;
    float w0 = 0.f, w1 = 0.f;
    int   gx = x0 + t;
    if (t < TILE_X) {
        float s  = g_s[b*HW + y*WID + gx];
        float ys = (float)y - s;
        float fy = floorf(ys);
        iy0 = (int)fy;
        w1 = ys - fy;
        w0 = 1.0f - w1;
    }

    const int og = (t >> 4) * 8;        // out-channel group base (0,8,...,56)
    const int pg = (t & 15) * 2;        // pixel pair base (0,2,...,30)

    float accU0[8], accU1[8], accL0[8], accL1[8];
    #pragma unroll
    for (int o = 0; o < 8; o++) { accU0[o]=0.f; accU1[o]=0.f; accL0[o]=0.f; accL1[o]=0.f; }

    for (int c = 0; c < CH; c++) {
        // ---- stage phase ----
        if (t < TILE_X) {
            // 4 rows x 3 cols gather from x2, then vertical interp -> 9 taps
            const float* x2c = g_x2 + (b*CH + c)*HW;
            float G[4][3];
            #pragma unroll
            for (int r = 0; r < 4; r++) {
                int row = iy0 - 1 + r;
                bool rok = (row >= 0) && (row < H);
                #pragma unroll
                for (int kx = 0; kx < 3; kx++) {
                    int col = gx - 1 + kx;
                    float v = 0.0f;
                    if (rok && col >= 0 && col < WID) v = x2c[row*WID + col];
                    G[r][kx] = v;
                }
            }
            #pragma unroll
            for (int ky = 0; ky < 3; ky++)
                #pragma unroll
                for (int kx = 0; kx < 3; kx++)
                    sV[t][ky*3+kx] = w0*G[ky][kx] + w1*G[ky+1][kx];
        } else {
            int tt = t - TILE_X;              // 0..95
            // weights: W[o, c, tap] -> sW[o*9+tap]
            const float* Wc = Wg + c*9;
            for (int i = tt; i < CH*9; i += 96) {
                int o = i / 9, tap = i - o*9;
                sW[i] = Wc[o*CH*9 + tap];
            }
            // upper halo: rows y-1..y+1, cols x0-1..x0+32
            const float* Xc = X + (b*CH + c)*HW;
            for (int i = tt; i < 3*(TILE_X+2); i += 96) {
                int r = i / (TILE_X+2), j = i - r*(TILE_X+2);
                int row = y - 1 + r, col = x0 - 1 + j;
                float v = 0.0f;
                if (row >= 0 && row < H && col >= 0 && col < WID) v = Xc[row*WID + col];
                sU[r][j] = v;
            }
        }
        __syncthreads();

        // ---- compute phase ----
        #pragma unroll
        for (int ky = 0; ky < 3; ky++) {
            #pragma unroll
            for (int kx = 0; kx < 3; kx++) {
                const int tap = ky*3 + kx;
                float u0 = sU[ky][pg + kx];
                float u1 = sU[ky][pg + 1 + kx];
                float v0 = sV[pg][tap];
                float v1 = sV[pg+1][tap];
                #pragma unroll
                for (int o = 0; o < 8; o++) {
                    float w = sW[(og + o)*9 + tap];
                    accU0[o] = fmaf(w, u0, accU0[o]);
                    accU1[o] = fmaf(w, u1, accU1[o]);
                    accL0[o] = fmaf(w, v0, accL0[o]);
                    accL1[o] = fmaf(w, v1, accL1[o]);
                }
            }
        }
        __syncthreads();
    }

    // epilogue: min(upper, lower)
    #pragma unroll
    for (int o = 0; o < 8; o++) {
        int oc = og + o;
        float* op = Out + ((b*CH + oc)*H + y)*WID + x0;
        op[pg]     = fminf(accU0[o], accL0[o]);
        op[pg + 1] = fminf(accU1[o], accL1[o]);
    }
}

// ---------------------------------------------------------------------------
extern "C" void kernel_launch(void* const* d_in, const int* in_sizes, int n_in,
                              void* d_out, int out_size) {
    const float* X  = (const float*)d_in[0];   // [4,64,256,256]
    const float* Wg = (const float*)d_in[1];   // [64,64,3,3]
    float* Out = (float*)d_out;                // [4,64,256,256]

    prep_kernel<<<(BATCH*HW + 255)/256, 256>>>(X);

    dim3 grid(WID/TILE_X, H, BATCH);
    conv_min_kernel<<<grid, 128>>>(X, Wg, Out);
}

// round 6
// speedup vs baseline: 1.6505x; 1.6505x over previous
#include <cuda_runtime.h>

#define BATCH 4
#define CH    64
#define H     256
#define WID   256
#define HW    (H*WID)
#define CHW   (CH*HW)
#define XT    64            // x-tile per block
#define C2ROWS 257          // rows -1..255, stored at index yy+1

// scratch (allocation-free: __device__ globals)
__device__ float g_s[BATCH*HW];                    // per-pixel vertical shift s
__device__ float g_x2[BATCH*CHW];                  // warped image
__device__ float g_C2[BATCH*CH*C2ROWS*WID];        // conv3x3(x2) at rows -1..255
__device__ float g_Wt[CH*CH*9];                    // weights transposed: [c][tap][oc]

// ---------------------------------------------------------------------------
// Kernel W: transpose weights [oc][c][tap] -> [c][tap][oc]
// ---------------------------------------------------------------------------
__global__ __launch_bounds__(256) void wt_kernel(const float* __restrict__ Wg) {
    int i = blockIdx.x * 256 + threadIdx.x;
    if (i >= CH*CH*9) return;
    int oc  = i / (CH*9);
    int rem = i - oc*CH*9;
    int c   = rem / 9;
    int tap = rem - c*9;
    g_Wt[c*(9*CH) + tap*CH + oc] = Wg[i];
}

// ---------------------------------------------------------------------------
// Kernel A: per-pixel channel max -> depth -> s, and vertical bilinear warp x2
// ---------------------------------------------------------------------------
__global__ __launch_bounds__(256) void prep_kernel(const float* __restrict__ X) {
    int idx = blockIdx.x * 256 + threadIdx.x;
    if (idx >= BATCH*HW) return;
    int b   = idx / HW;
    int rem = idx - b*HW;
    int y   = rem / WID;
    int x   = rem - y*WID;

    const float* Xpix = X + b*CHW + y*WID + x;
    float m = -1e30f;
    #pragma unroll 8
    for (int c = 0; c < CH; c++) m = fmaxf(m, Xpix[c*HW]);

    float depth = fminf(fmaxf(m, 1.0f), 50.0f);
    float s = 50.0f / (2.0f * depth);          // FOCAL/(downsample*depth)
    g_s[idx] = s;

    float ys = (float)y - s;
    float fy = floorf(ys);
    int   y0 = (int)fy;
    float w1 = ys - fy;
    float w0 = 1.0f - w1;

    bool ok0 = (y0   >= 0) && (y0   < H);
    bool ok1 = (y0+1 >= 0) && (y0+1 < H);
    const float* Xc0 = X + b*CHW + (ok0 ? y0   : 0)*WID + x;
    const float* Xc1 = X + b*CHW + (ok1 ? y0+1 : 0)*WID + x;
    float* X2p = g_x2 + b*CHW + y*WID + x;

    #pragma unroll 4
    for (int c = 0; c < CH; c++) {
        float a  = ok0 ? Xc0[c*HW] : 0.0f;
        float bb = ok1 ? Xc1[c*HW] : 0.0f;
        X2p[c*HW] = w0*a + w1*bb;
    }
}

// ---------------------------------------------------------------------------
// Generic tiled 3x3 conv, 64 oc x 64 px tile, 256 threads, 4 oc x 4 px/thread.
// FUSED=false: in = g_x2, center row yy = blockIdx.y - 1 in [-1,255],
//              write to g_C2 at row index yy+1.
// FUSED=true : in = X, row y = blockIdx.y, epilogue reads g_C2 at y0/y0+1,
//              out = min(upper, w0*C2[y0] + w1*C2[y0+1]).
// ---------------------------------------------------------------------------
template<bool FUSED>
__global__ __launch_bounds__(256) void conv_kernel(const float* __restrict__ in,
                                                   float* __restrict__ out) {
    __shared__ float sW[9*CH];          // tap-major, oc contiguous
    __shared__ float sIn[3][XT+2];

    const int x0 = blockIdx.x * XT;
    const int yy = FUSED ? (int)blockIdx.y : ((int)blockIdx.y - 1);  // center row
    const int b  = blockIdx.z;
    const int t  = threadIdx.x;

    const int ocb = (t & 15) * 4;       // out-channel base (lanes span oc)
    const int pxb = (t >> 4) * 4;       // pixel base within tile

    float acc[4][4];
    #pragma unroll
    for (int o = 0; o < 4; o++)
        #pragma unroll
        for (int p = 0; p < 4; p++) acc[o][p] = 0.0f;

    const float* inb = in + b*CHW;

    for (int c = 0; c < CH; c++) {
        __syncthreads();
        // stage weights (contiguous in g_Wt) and 3 halo rows
        {
            const float* Wc = g_Wt + c*(9*CH);
            #pragma unroll
            for (int i = t; i < 9*CH; i += 256) sW[i] = Wc[i];
            const float* Xc = inb + c*HW;
            for (int i = t; i < 3*(XT+2); i += 256) {
                int r = i / (XT+2), j = i - r*(XT+2);
                int row = yy - 1 + r, col = x0 - 1 + j;
                float v = 0.0f;
                if (row >= 0 && row < H && col >= 0 && col < WID)
                    v = __ldg(Xc + row*WID + col);
                sIn[r][j] = v;
            }
        }
        __syncthreads();

        #pragma unroll
        for (int ky = 0; ky < 3; ky++) {
            float r[6];
            #pragma unroll
            for (int j = 0; j < 6; j++) r[j] = sIn[ky][pxb + j];
            #pragma unroll
            for (int kx = 0; kx < 3; kx++) {
                const float4 w = *(const float4*)&sW[(ky*3+kx)*CH + ocb];
                #pragma unroll
                for (int p = 0; p < 4; p++) {
                    float v = r[kx + p];
                    acc[0][p] = fmaf(w.x, v, acc[0][p]);
                    acc[1][p] = fmaf(w.y, v, acc[1][p]);
                    acc[2][p] = fmaf(w.z, v, acc[2][p]);
                    acc[3][p] = fmaf(w.w, v, acc[3][p]);
                }
            }
        }
    }

    const int x = x0 + pxb;

    if (!FUSED) {
        // store conv(x2) at shifted row index yy+1
        #pragma unroll
        for (int o = 0; o < 4; o++) {
            float4 v = make_float4(acc[o][0], acc[o][1], acc[o][2], acc[o][3]);
            *(float4*)(g_C2 + (((long)(b*CH + ocb + o))*C2ROWS + (yy+1))*WID + x) = v;
        }
    } else {
        // lower = w0*C2[y0] + w1*C2[y0+1]; out = min(upper, lower)
        int   y0i[4];
        float w0f[4], w1f[4];
        #pragma unroll
        for (int p = 0; p < 4; p++) {
            float s  = g_s[b*HW + yy*WID + x + p];
            float ys = (float)yy - s;
            float fy = floorf(ys);
            y0i[p] = (int)fy;
            w1f[p] = ys - fy;
            w0f[p] = 1.0f - w1f[p];
        }
        #pragma unroll
        for (int o = 0; o < 4; o++) {
            const float* cc = g_C2 + ((long)(b*CH + ocb + o))*C2ROWS*WID + x;
            float4 v;
            float res[4];
            #pragma unroll
            for (int p = 0; p < 4; p++) {
                int y0 = y0i[p];
                float A = (y0 >= -1) ? cc[(y0+1)*WID + p] : 0.0f;
                float B = (y0 >= -2) ? cc[(y0+2)*WID + p] : 0.0f;
                float lower = w0f[p]*A + w1f[p]*B;
                res[p] = fminf(acc[o][p], lower);
            }
            v = make_float4(res[0], res[1], res[2], res[3]);
            *(float4*)(out + (((long)(b*CH + ocb + o))*H + yy)*WID + x) = v;
        }
    }
}

// ---------------------------------------------------------------------------
extern "C" void kernel_launch(void* const* d_in, const int* in_sizes, int n_in,
                              void* d_out, int out_size) {
    const float* X  = (const float*)d_in[0];   // [4,64,256,256]
    const float* Wg = (const float*)d_in[1];   // [64,64,3,3]
    float* Out = (float*)d_out;                // [4,64,256,256]

    wt_kernel<<<(CH*CH*9 + 255)/256, 256>>>(Wg);
    prep_kernel<<<(BATCH*HW + 255)/256, 256>>>(X);

    // C2 = conv3x3(x2) at center rows -1..255
    {
        float* x2p;  cudaGetSymbolAddress((void**)&x2p, g_x2);
        dim3 grid(WID/XT, C2ROWS, BATCH);
        conv_kernel<false><<<grid, 256>>>(x2p, nullptr);
    }
    // upper conv on X, fused interp + min epilogue
    {
        dim3 grid(WID/XT, H, BATCH);
        conv_kernel<true><<<grid, 256>>>(X, Out);
    }
}